// round 16
// baseline (speedup 1.0000x reference)
#include <cuda_runtime.h>
#include <cuda_bf16.h>
#include <cstdint>
#include <cstddef>

typedef unsigned long long ull;

#define B_  64
#define S_  200
#define T_  199
#define H_  256
#define G4  1024
#define NI_ 50000

#define CL  8           // CTAs per cluster
#define NCL 16          // clusters (16*4 = 64 batches)
#define THR 512         // 16 warps, fully warp-autonomous
#define TXB 2048u       // expect_tx: 8 CTAs x 32 elems x 8B per subgroup phase
#define K1_BLOCKS 1592  // 1592*8 warps = 199*64 (b,t) pairs exactly

// ------------------------- device scratch (no allocs allowed) ---------------
__device__ __align__(16) float g_xp[(size_t)T_ * B_ * G4];      // xp + bias, [t][b][1024]
__device__ __align__(16) float g_states[(size_t)T_ * B_ * H_];  // masked h outputs [t][b][256]
__device__ unsigned char g_mask[T_ * B_];
__device__ unsigned g_k3done;
__device__ float2 g_part[K1_BLOCKS];

// ------------------------- helpers ------------------------------------------
__device__ __forceinline__ ull pk2(float lo, float hi) {
    ull r; asm("mov.b64 %0, {%1, %2};" : "=l"(r) : "f"(lo), "f"(hi)); return r;
}
__device__ __forceinline__ void upk2(ull v, float& lo, float& hi) {
    asm("mov.b64 {%0, %1}, %2;" : "=f"(lo), "=f"(hi) : "l"(v));
}
__device__ __forceinline__ void fma2(ull& acc, ull a, ull b) {
    asm("fma.rn.f32x2 %0, %1, %2, %0;" : "+l"(acc) : "l"(a), "l"(b));
}
__device__ __forceinline__ ull add2(ull a, ull b) {
    ull r; asm("add.rn.f32x2 %0, %1, %2;" : "=l"(r) : "l"(a), "l"(b)); return r;
}
__device__ __forceinline__ float tanha(float x) {
    float y; asm("tanh.approx.f32 %0, %1;" : "=f"(y) : "f"(x)); return y;
}
__device__ __forceinline__ float siga(float x) {
    return fmaf(tanha(0.5f * x), 0.5f, 0.5f);
}
__device__ __forceinline__ unsigned smem_u32(const void* p) {
    unsigned a;
    asm("{ .reg .u64 t; cvta.to.shared.u64 t, %1; cvt.u32.u64 %0, t; }" : "=r"(a) : "l"(p));
    return a;
}
__device__ __forceinline__ unsigned ctarank_() {
    unsigned r; asm("mov.u32 %0, %%cluster_ctarank;" : "=r"(r)); return r;
}
__device__ __forceinline__ unsigned mapa_(unsigned addr, unsigned rank) {
    unsigned r; asm("mapa.shared::cluster.u32 %0, %1, %2;" : "=r"(r) : "r"(addr), "r"(rank));
    return r;
}
__device__ __forceinline__ void mbar_init(unsigned addr, unsigned cnt) {
    asm volatile("mbarrier.init.shared.b64 [%0], %1;" :: "r"(addr), "r"(cnt) : "memory");
}
__device__ __forceinline__ void mbar_expect_tx(unsigned addr, unsigned bytes) {
    asm volatile("mbarrier.arrive.expect_tx.shared.b64 _, [%0], %1;"
                 :: "r"(addr), "r"(bytes) : "memory");
}
// remote store whose completion posts tx bytes on the destination CTA's barrier
__device__ __forceinline__ void st_async64(unsigned raddr, ull v, unsigned rmbar) {
    asm volatile("st.async.shared::cluster.mbarrier::complete_tx::bytes.b64 [%0], %1, [%2];"
                 :: "r"(raddr), "l"(v), "r"(rmbar) : "memory");
}
__device__ __forceinline__ void mbar_wait(unsigned addr, int parity) {
    asm volatile(
        "{\n\t.reg .pred P;\n\t"
        "WL_%=:\n\t"
        "mbarrier.try_wait.parity.acquire.cta.shared::cta.b64 P, [%0], %1, 0x989680;\n\t"
        "@P bra.uni WD_%=;\n\t"
        "bra.uni WL_%=;\n\t"
        "WD_%=:\n\t}"
        :: "r"(addr), "r"(parity) : "memory");
}
__device__ __forceinline__ void cluster_sync_() {
    asm volatile("barrier.cluster.arrive.aligned;" ::: "memory");
    asm volatile("barrier.cluster.wait.aligned;" ::: "memory");
}

// ============================================================================
// K1: x_proj (+bias) -> g_xp, mask bytes, reset k3 flag. One warp per (b,t).
// ============================================================================
__global__ void k1_prep(const int* __restrict__ items, const int* __restrict__ actions,
                        const float* __restrict__ WihT, const float* __restrict__ b_lstm) {
    if (blockIdx.x == 0 && threadIdx.x == 0) g_k3done = 0u;
    int gw = blockIdx.x * 8 + (threadIdx.x >> 5);
    int lane = threadIdx.x & 31;
    if (gw >= T_ * B_) return;
    int b = gw & 63, t = gw >> 6;
    int it = items[b * S_ + t];
    int ac = actions[b * S_ + t];
    bool m = (it != 0);
    const float4* ra = (const float4*)(WihT + (size_t)it * G4);
    const float4* rb = (const float4*)(WihT + (size_t)(NI_ + ac) * G4);
    const float4* bi = (const float4*)b_lstm;
    float4* dst = (float4*)(g_xp + ((size_t)t * B_ + b) * G4);
#pragma unroll
    for (int p = 0; p < 8; p++) {
        int idx = lane + 32 * p;
        float4 bv = bi[idx];
        float4 o;
        if (m) {
            float4 a = ra[idx], c = rb[idx];
            o = make_float4(a.x + c.x + bv.x, a.y + c.y + bv.y,
                            a.z + c.z + bv.z, a.w + c.w + bv.w);
        } else {
            o = bv;
        }
        dst[idx] = o;
    }
    if (lane == 0) g_mask[t * B_ + b] = m ? 1 : 0;
}

// profiling-alignment no-ops (2 launches so ncu -s 5 -c 1 lands on k2_lstm)
__global__ void knop() {}

// ============================================================================
// K2: warp-autonomous pipelined LSTM. 16 clusters x 8 CTAs; cluster owns 4
// batches split into subgroups A={b0,b0+1}, B={b0+2,b0+3}. CTA rank r owns
// 128 gate rows (32 h-elems x 4 gates), K=256.
// Warp w owns elems {2w, 2w+1} WITH all 4 gate columns: lane = (col 0..7,
// K-quarter 0..3), 64 K per lane. Reduction = 2 shfl.bfly (over K-quarters);
// gate gather = 3 shfl.idx; lanes 0/16 do activations + st.async to 8 peers.
// NO smp, NO named barrier, NO owner warps — only the mbarrier wait remains.
// ============================================================================
__global__ void __launch_bounds__(THR, 1) __cluster_dims__(CL, 1, 1)
k2_lstm(const float* __restrict__ Whh) {
    __shared__ __align__(16) ull smh[2][2][256];   // [sg][buf][j] = {h_b0,h_b1}
    __shared__ __align__(8)  ull mbar[4];          // [sg*2+buf]

    const int tid = threadIdx.x;
    const int lane = tid & 31;
    const int w = tid >> 5;            // warp 0..15 -> elems {2w, 2w+1}
    const unsigned rank = ctarank_();
    const int b0 = (blockIdx.x >> 3) * 4;

    const int cl   = lane >> 2;        // col-in-warp 0..7
    const int kq   = lane & 3;         // K-quarter: j in [64kq, 64kq+64)
    const int gate = cl & 3;
    const int eLoc = cl >> 2;          // 0..1
    const bool isK0  = (kq == 0);
    const bool isAct = (lane == 0) || (lane == 16);
    const int jg = 32 * (int)rank + 2 * w + eLoc;   // global h index (act lanes)
    const int rowG = gate * 256 + jg;               // global gate row of my col

    // zero h buffers (8 KB); init + pre-arm all 4 barriers
    for (int i = tid; i < 512; i += THR)
        ((float4*)smh)[i] = make_float4(0.f, 0.f, 0.f, 0.f);
    if (tid < 4) mbar_init(smem_u32(&mbar[tid]), 1);
    __syncthreads();
    if (tid == 0) {
#pragma unroll
        for (int i = 0; i < 4; i++) mbar_expect_tx(smem_u32(&mbar[i]), TXB);
    }
    __syncthreads();
    cluster_sync_();   // arming + zeroed tiles visible before any peer store

    const unsigned mbA0 = smem_u32(&mbar[0]), mbA1 = smem_u32(&mbar[1]);
    const unsigned mbB0 = smem_u32(&mbar[2]), mbB1 = smem_u32(&mbar[3]);

    // weights: my col rowG, K-slice [64kq, 64kq+64). First 32 pre-packed {v,v}.
    ull   W1p[32];
    float W2[32];
    {
        const float4* p1 = (const float4*)(Whh + (size_t)rowG * H_ + kq * 64);
        const float4* p2 = (const float4*)(Whh + (size_t)rowG * H_ + kq * 64 + 32);
#pragma unroll
        for (int q4 = 0; q4 < 8; q4++) {
            float4 v = p1[q4];
            W1p[q4 * 4 + 0] = pk2(v.x, v.x); W1p[q4 * 4 + 1] = pk2(v.y, v.y);
            W1p[q4 * 4 + 2] = pk2(v.z, v.z); W1p[q4 * 4 + 3] = pk2(v.w, v.w);
            float4 u = p2[q4];
            W2[q4 * 4 + 0] = u.x; W2[q4 * 4 + 1] = u.y;
            W2[q4 * 4 + 2] = u.z; W2[q4 * 4 + 3] = u.w;
        }
    }

    // per-subgroup state (act lanes) and xp pairs (k0 lanes)
    float c0A = 0.f, c1A = 0.f, h0A = 0.f, h1A = 0.f;
    float c0B = 0.f, c1B = 0.f, h0B = 0.f, h1B = 0.f;
    uchar2 mvA = make_uchar2(0, 0), mvB = make_uchar2(0, 0);
    ull xpA = 0, xpB = 0;
    const float* xpPA = g_xp + (size_t)b0 * G4 + rowG;        // sg A, batch b0
    const float* xpPB = g_xp + (size_t)(b0 + 2) * G4 + rowG;  // sg B, batch b0+2
    if (isK0) {
        xpA = pk2(xpPA[0], xpPA[G4]);
        xpB = pk2(xpPB[0], xpPB[G4]);
    }
    if (isAct) {
        mvA = *(const uchar2*)(g_mask + b0);
        mvB = *(const uchar2*)(g_mask + b0 + 2);
    }

    for (int t = 0; t < T_; t++) {
        const int buf = t & 1;
        const int par = ((t >> 1) + (t & 1) + 1) & 1;

        // ================= subgroup A =================
        if (t > 0) {
            mbar_wait(buf ? mbA1 : mbA0, par);
            if (tid == 0) mbar_expect_tx(buf ? mbA1 : mbA0, TXB);
        }
        {
            ull a1 = 0, a2 = 0;
            const ulonglong2* hb = (const ulonglong2*)&smh[0][buf][kq * 64];
#pragma unroll
            for (int j2 = 0; j2 < 16; j2++) {
                ulonglong2 hx = hb[j2];
                fma2(a1, W1p[2 * j2],     hx.x);
                fma2(a2, W1p[2 * j2 + 1], hx.y);
            }
#pragma unroll
            for (int j2 = 0; j2 < 16; j2++) {
                ulonglong2 hx = hb[16 + j2];
                fma2(a1, pk2(W2[2 * j2],     W2[2 * j2]),     hx.x);
                fma2(a2, pk2(W2[2 * j2 + 1], W2[2 * j2 + 1]), hx.y);
            }
            ull acc = add2(a1, a2);
            acc = add2(acc, __shfl_xor_sync(0xffffffffu, acc, 1));
            acc = add2(acc, __shfl_xor_sync(0xffffffffu, acc, 2));
            if (isK0) acc = add2(acc, xpA);
            if (isK0 && t + 1 < T_) {
                const float* xp = xpPA + (size_t)(t + 1) * B_ * G4;
                xpA = pk2(xp[0], xp[G4]);
            }
            ull aF = __shfl_sync(0xffffffffu, acc, (lane & 16) + 4);
            ull aG = __shfl_sync(0xffffffffu, acc, (lane & 16) + 8);
            ull aO = __shfl_sync(0xffffffffu, acc, (lane & 16) + 12);
            if (isAct) {
                float i0, i1, f0, f1, g0, g1, o0, o1;
                upk2(acc, i0, i1); upk2(aF, f0, f1);
                upk2(aG, g0, g1); upk2(aO, o0, o1);
                float out0, out1;
                {
                    float ii = siga(i0), ff = siga(f0), gt = tanha(g0), oo = siga(o0);
                    float cn = ff * c0A + ii * gt;
                    float hn = oo * tanha(cn);
                    if (mvA.x) { c0A = cn; h0A = hn; out0 = hn; } else out0 = 0.f;
                }
                {
                    float ii = siga(i1), ff = siga(f1), gt = tanha(g1), oo = siga(o1);
                    float cn = ff * c1A + ii * gt;
                    float hn = oo * tanha(cn);
                    if (mvA.y) { c1A = cn; h1A = hn; out1 = hn; } else out1 = 0.f;
                }
                if (t + 1 < T_) {
                    ull hull = pk2(h0A, h1A);
                    unsigned loc = smem_u32(&smh[0][1 - buf][jg]);
                    unsigned mbn = buf ? mbA0 : mbA1;
#pragma unroll
                    for (int rr = 0; rr < CL; rr++)
                        st_async64(mapa_(loc, rr), hull, mapa_(mbn, rr));
                }
                float* sp = g_states + ((size_t)t * B_ + b0) * H_ + jg;
                sp[0]  = out0;
                sp[H_] = out1;
                if (t + 1 < T_) mvA = *(const uchar2*)(g_mask + (t + 1) * B_ + b0);
            }
        }

        // ================= subgroup B =================
        if (t > 0) {
            mbar_wait(buf ? mbB1 : mbB0, par);
            if (tid == 0) mbar_expect_tx(buf ? mbB1 : mbB0, TXB);
        }
        {
            ull a1 = 0, a2 = 0;
            const ulonglong2* hb = (const ulonglong2*)&smh[1][buf][kq * 64];
#pragma unroll
            for (int j2 = 0; j2 < 16; j2++) {
                ulonglong2 hx = hb[j2];
                fma2(a1, W1p[2 * j2],     hx.x);
                fma2(a2, W1p[2 * j2 + 1], hx.y);
            }
#pragma unroll
            for (int j2 = 0; j2 < 16; j2++) {
                ulonglong2 hx = hb[16 + j2];
                fma2(a1, pk2(W2[2 * j2],     W2[2 * j2]),     hx.x);
                fma2(a2, pk2(W2[2 * j2 + 1], W2[2 * j2 + 1]), hx.y);
            }
            ull acc = add2(a1, a2);
            acc = add2(acc, __shfl_xor_sync(0xffffffffu, acc, 1));
            acc = add2(acc, __shfl_xor_sync(0xffffffffu, acc, 2));
            if (isK0) acc = add2(acc, xpB);
            if (isK0 && t + 1 < T_) {
                const float* xp = xpPB + (size_t)(t + 1) * B_ * G4;
                xpB = pk2(xp[0], xp[G4]);
            }
            ull aF = __shfl_sync(0xffffffffu, acc, (lane & 16) + 4);
            ull aG = __shfl_sync(0xffffffffu, acc, (lane & 16) + 8);
            ull aO = __shfl_sync(0xffffffffu, acc, (lane & 16) + 12);
            if (isAct) {
                float i0, i1, f0, f1, g0, g1, o0, o1;
                upk2(acc, i0, i1); upk2(aF, f0, f1);
                upk2(aG, g0, g1); upk2(aO, o0, o1);
                float out0, out1;
                {
                    float ii = siga(i0), ff = siga(f0), gt = tanha(g0), oo = siga(o0);
                    float cn = ff * c0B + ii * gt;
                    float hn = oo * tanha(cn);
                    if (mvB.x) { c0B = cn; h0B = hn; out0 = hn; } else out0 = 0.f;
                }
                {
                    float ii = siga(i1), ff = siga(f1), gt = tanha(g1), oo = siga(o1);
                    float cn = ff * c1B + ii * gt;
                    float hn = oo * tanha(cn);
                    if (mvB.y) { c1B = cn; h1B = hn; out1 = hn; } else out1 = 0.f;
                }
                if (t + 1 < T_) {
                    ull hull = pk2(h0B, h1B);
                    unsigned loc = smem_u32(&smh[1][1 - buf][jg]);
                    unsigned mbn = buf ? mbB0 : mbB1;
#pragma unroll
                    for (int rr = 0; rr < CL; rr++)
                        st_async64(mapa_(loc, rr), hull, mapa_(mbn, rr));
                }
                float* sp = g_states + ((size_t)t * B_ + b0 + 2) * H_ + jg;
                sp[0]  = out0;
                sp[H_] = out1;
                if (t + 1 < T_) mvB = *(const uchar2*)(g_mask + (t + 1) * B_ + b0 + 2);
            }
        }
    }
    cluster_sync_();  // no CTA exits while peers' remote ops may be in flight
}

// ============================================================================
// K3: query logits + per-(b,t) NLL; block partials + fused deterministic
// last-block final reduction. One warp per (b,t).
// ============================================================================
__global__ void k3_loss(const int* __restrict__ items, const int* __restrict__ actions,
                        const float* __restrict__ temb, const float* __restrict__ Wq,
                        const float* __restrict__ bq, float* __restrict__ out) {
    __shared__ float2 sred[8];
    __shared__ unsigned slast;
    int gw = blockIdx.x * 8 + (threadIdx.x >> 5);
    int lane = threadIdx.x & 31;
    float nll = 0.f, cnt = 0.f;
    int b = gw & 63, t = gw >> 6;
    int qit = items[b * S_ + t + 1];
    if (qit != 0) {
        const float4* sv = (const float4*)(g_states + ((size_t)t * B_ + b) * H_);
        const float4* ev = (const float4*)(temb + (size_t)qit * H_);
        const float4* w0 = (const float4*)Wq;
        const float4* w1 = (const float4*)(Wq + H_);
        float d0 = 0.f, d1 = 0.f;
#pragma unroll
        for (int p = 0; p < 2; p++) {
            int idx = lane * 2 + p;
            float4 s = sv[idx], e = ev[idx], a = w0[idx], c = w1[idx];
            float es;
            es = e.x * s.x; d0 += es * a.x; d1 += es * c.x;
            es = e.y * s.y; d0 += es * a.y; d1 += es * c.y;
            es = e.z * s.z; d0 += es * a.z; d1 += es * c.z;
            es = e.w * s.w; d0 += es * a.w; d1 += es * c.w;
        }
        ull d = pk2(d0, d1);
#pragma unroll
        for (int off = 16; off; off >>= 1)
            d = add2(d, __shfl_xor_sync(0xffffffffu, d, off));
        upk2(d, d0, d1);
        if (lane == 0) {
            float q0 = d0 + bq[0], q1 = d1 + bq[1];
            int tgt = actions[b * S_ + t + 1];
            float mx = fmaxf(q0, q1), mn = fminf(q0, q1);
            float lse = mx + log1pf(__expf(mn - mx));
            nll = lse - (tgt ? q1 : q0);
            cnt = 1.f;
        }
    }
    if (lane == 0) sred[threadIdx.x >> 5] = make_float2(nll, cnt);
    __syncthreads();
    if (threadIdx.x == 0) {
        float s = 0.f, c = 0.f;
#pragma unroll
        for (int i = 0; i < 8; i++) { s += sred[i].x; c += sred[i].y; }
        g_part[blockIdx.x] = make_float2(s, c);
        __threadfence();
        unsigned o = atomicAdd(&g_k3done, 1u);
        slast = (o == K1_BLOCKS - 1) ? 1u : 0u;
    }
    __syncthreads();
    if (slast) {
        __shared__ float ss[256], sc[256];
        __threadfence();
        float s = 0.f, c = 0.f;
        for (int i = threadIdx.x; i < K1_BLOCKS; i += 256) {
            float2 v = g_part[i];
            s += v.x; c += v.y;
        }
        ss[threadIdx.x] = s; sc[threadIdx.x] = c;
        __syncthreads();
        for (int st = 128; st; st >>= 1) {
            if (threadIdx.x < st) {
                ss[threadIdx.x] += ss[threadIdx.x + st];
                sc[threadIdx.x] += sc[threadIdx.x + st];
            }
            __syncthreads();
        }
        if (threadIdx.x == 0) out[0] = ss[0] / sc[0];
    }
}

// ============================================================================
extern "C" void kernel_launch(void* const* d_in, const int* in_sizes, int n_in,
                              void* d_out, int out_size) {
    const int*   items   = (const int*)d_in[0];
    const int*   actions = (const int*)d_in[1];
    const float* WihT    = (const float*)d_in[2];
    const float* Whh     = (const float*)d_in[3];
    const float* b_lstm  = (const float*)d_in[4];
    const float* temb    = (const float*)d_in[5];
    const float* Wq      = (const float*)d_in[6];
    const float* bq      = (const float*)d_in[7];
    (void)in_sizes; (void)n_in; (void)out_size;

    k1_prep<<<K1_BLOCKS, 256>>>(items, actions, WihT, b_lstm);
    knop<<<1, 1>>>();   // alignment: put k2_lstm at ncu's profiled slot (-s 5)
    knop<<<1, 1>>>();
    k2_lstm<<<NCL * CL, THR>>>(Whh);
    k3_loss<<<K1_BLOCKS, 256>>>(items, actions, temb, Wq, bq, (float*)d_out);
}

// round 17
// speedup vs baseline: 7.9564x; 7.9564x over previous
#include <cuda_runtime.h>
#include <cuda_bf16.h>
#include <cstdint>
#include <cstddef>

typedef unsigned long long ull;

#define B_  64
#define S_  200
#define T_  199
#define H_  256
#define G4  1024
#define NI_ 50000

#define CL  8           // CTAs per cluster
#define NCL 16          // clusters (16*4 = 64 batches)
#define CPT 512         // compute threads
#define THR 576         // + 2 owner warps (subgroup A, subgroup B)
#define BARCNT 544      // 512 compute + 32 owners of one subgroup
#define TXB 2048u       // expect_tx: 8 CTAs x 32 owners x 8B per subgroup
#define K1_BLOCKS 1592  // 1592*8 warps = 199*64 (b,t) pairs exactly

// ------------------------- device scratch (no allocs allowed) ---------------
__device__ __align__(16) float g_xp[(size_t)T_ * B_ * G4];      // xp + bias, [t][b][1024]
__device__ __align__(16) float g_states[(size_t)T_ * B_ * H_];  // masked h outputs [t][b][256]
__device__ unsigned char g_mask[T_ * B_];
__device__ unsigned g_k3done;
__device__ float2 g_part[K1_BLOCKS];

// ------------------------- helpers ------------------------------------------
__device__ __forceinline__ ull pk2(float lo, float hi) {
    ull r; asm("mov.b64 %0, {%1, %2};" : "=l"(r) : "f"(lo), "f"(hi)); return r;
}
__device__ __forceinline__ void upk2(ull v, float& lo, float& hi) {
    asm("mov.b64 {%0, %1}, %2;" : "=f"(lo), "=f"(hi) : "l"(v));
}
__device__ __forceinline__ void fma2(ull& acc, ull a, ull b) {
    asm("fma.rn.f32x2 %0, %1, %2, %0;" : "+l"(acc) : "l"(a), "l"(b));
}
__device__ __forceinline__ ull add2(ull a, ull b) {
    ull r; asm("add.rn.f32x2 %0, %1, %2;" : "=l"(r) : "l"(a), "l"(b)); return r;
}
__device__ __forceinline__ float tanha(float x) {
    float y; asm("tanh.approx.f32 %0, %1;" : "=f"(y) : "f"(x)); return y;
}
__device__ __forceinline__ float siga(float x) {
    return fmaf(tanha(0.5f * x), 0.5f, 0.5f);
}
__device__ __forceinline__ unsigned smem_u32(const void* p) {
    unsigned a;
    asm("{ .reg .u64 t; cvta.to.shared.u64 t, %1; cvt.u32.u64 %0, t; }" : "=r"(a) : "l"(p));
    return a;
}
__device__ __forceinline__ unsigned ctarank_() {
    unsigned r; asm("mov.u32 %0, %%cluster_ctarank;" : "=r"(r)); return r;
}
__device__ __forceinline__ unsigned mapa_(unsigned addr, unsigned rank) {
    unsigned r; asm("mapa.shared::cluster.u32 %0, %1, %2;" : "=r"(r) : "r"(addr), "r"(rank));
    return r;
}
__device__ __forceinline__ void mbar_init(unsigned addr, unsigned cnt) {
    asm volatile("mbarrier.init.shared.b64 [%0], %1;" :: "r"(addr), "r"(cnt) : "memory");
}
__device__ __forceinline__ void mbar_expect_tx(unsigned addr, unsigned bytes) {
    asm volatile("mbarrier.arrive.expect_tx.shared.b64 _, [%0], %1;"
                 :: "r"(addr), "r"(bytes) : "memory");
}
// remote store whose completion posts tx bytes on the destination CTA's barrier
__device__ __forceinline__ void st_async64(unsigned raddr, ull v, unsigned rmbar) {
    asm volatile("st.async.shared::cluster.mbarrier::complete_tx::bytes.b64 [%0], %1, [%2];"
                 :: "r"(raddr), "l"(v), "r"(rmbar) : "memory");
}
__device__ __forceinline__ void mbar_wait(unsigned addr, int parity) {
    asm volatile(
        "{\n\t.reg .pred P;\n\t"
        "WL_%=:\n\t"
        "mbarrier.try_wait.parity.acquire.cta.shared::cta.b64 P, [%0], %1, 0x989680;\n\t"
        "@P bra.uni WD_%=;\n\t"
        "bra.uni WL_%=;\n\t"
        "WD_%=:\n\t}"
        :: "r"(addr), "r"(parity) : "memory");
}
__device__ __forceinline__ void cluster_sync_() {
    asm volatile("barrier.cluster.arrive.aligned;" ::: "memory");
    asm volatile("barrier.cluster.wait.aligned;" ::: "memory");
}

// ============================================================================
// K1: x_proj (+bias) -> g_xp, mask bytes, reset k3 flag. One warp per (b,t).
// ============================================================================
__global__ void k1_prep(const int* __restrict__ items, const int* __restrict__ actions,
                        const float* __restrict__ WihT, const float* __restrict__ b_lstm) {
    if (blockIdx.x == 0 && threadIdx.x == 0) g_k3done = 0u;
    int gw = blockIdx.x * 8 + (threadIdx.x >> 5);
    int lane = threadIdx.x & 31;
    if (gw >= T_ * B_) return;
    int b = gw & 63, t = gw >> 6;
    int it = items[b * S_ + t];
    int ac = actions[b * S_ + t];
    bool m = (it != 0);
    const float4* ra = (const float4*)(WihT + (size_t)it * G4);
    const float4* rb = (const float4*)(WihT + (size_t)(NI_ + ac) * G4);
    const float4* bi = (const float4*)b_lstm;
    float4* dst = (float4*)(g_xp + ((size_t)t * B_ + b) * G4);
#pragma unroll
    for (int p = 0; p < 8; p++) {
        int idx = lane + 32 * p;
        float4 bv = bi[idx];
        float4 o;
        if (m) {
            float4 a = ra[idx], c = rb[idx];
            o = make_float4(a.x + c.x + bv.x, a.y + c.y + bv.y,
                            a.z + c.z + bv.z, a.w + c.w + bv.w);
        } else {
            o = bv;
        }
        dst[idx] = o;
    }
    if (lane == 0) g_mask[t * B_ + b] = m ? 1 : 0;
}

// profiling-alignment no-ops (2 launches so ncu -s 5 -c 1 lands on k2_lstm)
__global__ void knop() {}

// ============================================================================
// K2: pipelined LSTM (R11 backbone — best known). 16 clusters x 8 CTAs;
// cluster owns 4 batches split into subgroups A={b0,b0+1}, B={b0+2,b0+3}.
// CTA rank r owns 128 gate rows (32 h-elems x 4 gates), K=256. Whh register-
// resident in compute warps; dedicated owner warp per subgroup; producers
// flow through via bar.arrive. h exchange: tx-completing st.async into
// peers' double-buffered h tiles.
// CHANGE vs R11: owner mapa address tables precomputed outside the t-loop
// (removes ~16 ALU ops from the owner critical chain per phase).
// ============================================================================
__global__ void __launch_bounds__(THR, 1) __cluster_dims__(CL, 1, 1)
k2_lstm(const float* __restrict__ Whh) {
    __shared__ __align__(16) ull smh[2][2][256];   // [sg][buf][j] = {h_b0,h_b1}
    __shared__ __align__(16) ull smp[2][8][128];   // [sg][ks][col]
    __shared__ __align__(8)  ull mbar[4];          // [sg*2+buf]

    const int tid = threadIdx.x;
    const unsigned rank = ctarank_();
    const int b0 = (blockIdx.x >> 3) * 4;

    // zero h buffers (8 KB); init + pre-arm all 4 barriers
    for (int i = tid; i < 512; i += THR)
        ((float4*)smh)[i] = make_float4(0.f, 0.f, 0.f, 0.f);
    if (tid < 4) mbar_init(smem_u32(&mbar[tid]), 1);
    __syncthreads();
    if (tid == 0) {
#pragma unroll
        for (int i = 0; i < 4; i++) mbar_expect_tx(smem_u32(&mbar[i]), TXB);
    }
    __syncthreads();
    cluster_sync_();   // arming + zeroed tiles visible before any peer store

    const unsigned mbA0 = smem_u32(&mbar[0]), mbA1 = smem_u32(&mbar[1]);
    const unsigned mbB0 = smem_u32(&mbar[2]), mbB1 = smem_u32(&mbar[3]);

    if (tid < CPT) {
        // ---------------- compute role (identical to R11 winner) ------------
        const int ks = tid >> 6;    // K-slice: j in [32ks, 32ks+32)
        const int u  = tid & 63;    // cols u and u+64

        ull   W1p[32];
        float W2[32];
        {
            const int r1 = (u >> 5) * 256 + 32 * (int)rank + (u & 31);
            const int r2 = (2 + (u >> 5)) * 256 + 32 * (int)rank + (u & 31);
            const float4* p1 = (const float4*)(Whh + (size_t)r1 * H_ + ks * 32);
            const float4* p2 = (const float4*)(Whh + (size_t)r2 * H_ + ks * 32);
#pragma unroll
            for (int q4 = 0; q4 < 8; q4++) {
                float4 v = p1[q4];
                W1p[q4 * 4 + 0] = pk2(v.x, v.x); W1p[q4 * 4 + 1] = pk2(v.y, v.y);
                W1p[q4 * 4 + 2] = pk2(v.z, v.z); W1p[q4 * 4 + 3] = pk2(v.w, v.w);
                float4 w = p2[q4];
                W2[q4 * 4 + 0] = w.x; W2[q4 * 4 + 1] = w.y;
                W2[q4 * 4 + 2] = w.z; W2[q4 * 4 + 3] = w.w;
            }
        }

        for (int t = 0; t < T_; t++) {
            const int buf = t & 1;
            const int par = ((t >> 1) + (t & 1) + 1) & 1;

            // ---- subgroup A ----
            if (t > 0) mbar_wait(buf ? mbA1 : mbA0, par);
            {
                ull a1 = 0, a2 = 0;
                const ulonglong2* hb = (const ulonglong2*)&smh[0][buf][ks * 32];
#pragma unroll
                for (int j2 = 0; j2 < 16; j2++) {
                    ulonglong2 hx = hb[j2];
                    fma2(a1, W1p[2 * j2], hx.x);
                    fma2(a2, pk2(W2[2 * j2], W2[2 * j2]), hx.x);
                    fma2(a1, W1p[2 * j2 + 1], hx.y);
                    fma2(a2, pk2(W2[2 * j2 + 1], W2[2 * j2 + 1]), hx.y);
                }
                smp[0][ks][u]      = a1;
                smp[0][ks][u + 64] = a2;
            }
            asm volatile("bar.arrive 2, %0;" :: "n"(BARCNT) : "memory");

            // ---- subgroup B ----
            if (t > 0) mbar_wait(buf ? mbB1 : mbB0, par);
            {
                ull a1 = 0, a2 = 0;
                const ulonglong2* hb = (const ulonglong2*)&smh[1][buf][ks * 32];
#pragma unroll
                for (int j2 = 0; j2 < 16; j2++) {
                    ulonglong2 hx = hb[j2];
                    fma2(a1, W1p[2 * j2], hx.x);
                    fma2(a2, pk2(W2[2 * j2], W2[2 * j2]), hx.x);
                    fma2(a1, W1p[2 * j2 + 1], hx.y);
                    fma2(a2, pk2(W2[2 * j2 + 1], W2[2 * j2 + 1]), hx.y);
                }
                smp[1][ks][u]      = a1;
                smp[1][ks][u + 64] = a2;
            }
            asm volatile("bar.arrive 3, %0;" :: "n"(BARCNT) : "memory");
        }
    } else {
        // ---------------- owner role (2 warps: sg 0 = A, sg 1 = B) ----------
        const int ot = tid - CPT;          // 0..63
        const int sg = ot >> 5;            // subgroup
        const int e  = ot & 31;            // h-elem within CTA
        const int bA = b0 + 2 * sg;        // batch pair (bA, bA+1)
        const int jg = 32 * (int)rank + e; // global h index owned
        const unsigned mb0 = sg ? mbB0 : mbA0;
        const unsigned mb1 = sg ? mbB1 : mbA1;

        // precompute all remote addresses (both buffers + both barriers)
        unsigned locs[2][CL], mbns[2][CL];
        {
            unsigned l0 = smem_u32(&smh[sg][0][jg]);
            unsigned l1 = smem_u32(&smh[sg][1][jg]);
#pragma unroll
            for (int rr = 0; rr < CL; rr++) {
                locs[0][rr] = mapa_(l0, rr);
                locs[1][rr] = mapa_(l1, rr);
                mbns[0][rr] = mapa_(mb0, rr);
                mbns[1][rr] = mapa_(mb1, rr);
            }
        }

        float c0 = 0.f, c1 = 0.f, h0 = 0.f, h1 = 0.f;
        uchar2 mv = *(const uchar2*)(g_mask + bA);
        const float* xb0 = g_xp + (size_t)bA * G4 + jg;   // + g*256; + G4 for bA+1
        float xq0a = xb0[0],   xq0b = xb0[G4];
        float xq1a = xb0[256], xq1b = xb0[G4 + 256];
        float xq2a = xb0[512], xq2b = xb0[G4 + 512];
        float xq3a = xb0[768], xq3b = xb0[G4 + 768];

        for (int t = 0; t < T_; t++) {
            const int buf = t & 1;
            const int par = ((t >> 1) + (t & 1) + 1) & 1;
            const unsigned mba = buf ? mb1 : mb0;
            if (t > 0) {
                mbar_wait(mba, par);                   // observe flip
                if (e == 0) mbar_expect_tx(mba, TXB);  // re-arm for t+2: one lane
            }
            if (sg == 0)
                asm volatile("bar.sync 2, %0;" :: "n"(BARCNT) : "memory");
            else
                asm volatile("bar.sync 3, %0;" :: "n"(BARCNT) : "memory");

            // reduce 8 K-slices x 4 gates (32 conflict-free LDS.64 + 28 add2)
            ull s0 = smp[sg][0][e],      s1 = smp[sg][0][32 + e],
                s2 = smp[sg][0][64 + e], s3 = smp[sg][0][96 + e];
#pragma unroll
            for (int k = 1; k < 8; k++) {
                s0 = add2(s0, smp[sg][k][e]);
                s1 = add2(s1, smp[sg][k][32 + e]);
                s2 = add2(s2, smp[sg][k][64 + e]);
                s3 = add2(s3, smp[sg][k][96 + e]);
            }
            s0 = add2(s0, pk2(xq0a, xq0b));
            s1 = add2(s1, pk2(xq1a, xq1b));
            s2 = add2(s2, pk2(xq2a, xq2b));
            s3 = add2(s3, pk2(xq3a, xq3b));

            float i0, i1, f0, f1, gg0, gg1, o0, o1;
            upk2(s0, i0, i1); upk2(s1, f0, f1); upk2(s2, gg0, gg1); upk2(s3, o0, o1);

            float out0, out1;
            {
                float ii = siga(i0), ff = siga(f0), gt = tanha(gg0), oo = siga(o0);
                float cn = ff * c0 + ii * gt;
                float hn = oo * tanha(cn);
                if (mv.x) { c0 = cn; h0 = hn; out0 = hn; } else out0 = 0.f;
            }
            {
                float ii = siga(i1), ff = siga(f1), gt = tanha(gg1), oo = siga(o1);
                float cn = ff * c1 + ii * gt;
                float hn = oo * tanha(cn);
                if (mv.y) { c1 = cn; h1 = hn; out1 = hn; } else out1 = 0.f;
            }

            // broadcast h(t+1) first (critical path): precomputed addresses
            if (t + 1 < T_) {
                ull hull = pk2(h0, h1);
                const int nb = 1 - buf;
#pragma unroll
                for (int rr = 0; rr < CL; rr++)
                    st_async64(locs[nb][rr], hull, mbns[nb][rr]);
            }

            // off critical path: states store + next-step prefetch
            float* sp = g_states + ((size_t)t * B_ + bA) * H_ + jg;
            sp[0]  = out0;
            sp[H_] = out1;
            if (t + 1 < T_) {
                const float* xp = xb0 + (size_t)(t + 1) * B_ * G4;
                xq0a = xp[0];   xq0b = xp[G4];
                xq1a = xp[256]; xq1b = xp[G4 + 256];
                xq2a = xp[512]; xq2b = xp[G4 + 512];
                xq3a = xp[768]; xq3b = xp[G4 + 768];
                mv = *(const uchar2*)(g_mask + (t + 1) * B_ + bA);
            }
        }
    }
    cluster_sync_();  // no CTA exits while peers' remote ops may be in flight
}

// ============================================================================
// K3: query logits + per-(b,t) NLL; block partials + fused deterministic
// last-block final reduction. One warp per (b,t).
// ============================================================================
__global__ void k3_loss(const int* __restrict__ items, const int* __restrict__ actions,
                        const float* __restrict__ temb, const float* __restrict__ Wq,
                        const float* __restrict__ bq, float* __restrict__ out) {
    __shared__ float2 sred[8];
    __shared__ unsigned slast;
    int gw = blockIdx.x * 8 + (threadIdx.x >> 5);
    int lane = threadIdx.x & 31;
    float nll = 0.f, cnt = 0.f;
    int b = gw & 63, t = gw >> 6;
    int qit = items[b * S_ + t + 1];
    if (qit != 0) {
        const float4* sv = (const float4*)(g_states + ((size_t)t * B_ + b) * H_);
        const float4* ev = (const float4*)(temb + (size_t)qit * H_);
        const float4* w0 = (const float4*)Wq;
        const float4* w1 = (const float4*)(Wq + H_);
        float d0 = 0.f, d1 = 0.f;
#pragma unroll
        for (int p = 0; p < 2; p++) {
            int idx = lane * 2 + p;
            float4 s = sv[idx], e = ev[idx], a = w0[idx], c = w1[idx];
            float es;
            es = e.x * s.x; d0 += es * a.x; d1 += es * c.x;
            es = e.y * s.y; d0 += es * a.y; d1 += es * c.y;
            es = e.z * s.z; d0 += es * a.z; d1 += es * c.z;
            es = e.w * s.w; d0 += es * a.w; d1 += es * c.w;
        }
        ull d = pk2(d0, d1);
#pragma unroll
        for (int off = 16; off; off >>= 1)
            d = add2(d, __shfl_xor_sync(0xffffffffu, d, off));
        upk2(d, d0, d1);
        if (lane == 0) {
            float q0 = d0 + bq[0], q1 = d1 + bq[1];
            int tgt = actions[b * S_ + t + 1];
            float mx = fmaxf(q0, q1), mn = fminf(q0, q1);
            float lse = mx + log1pf(__expf(mn - mx));
            nll = lse - (tgt ? q1 : q0);
            cnt = 1.f;
        }
    }
    if (lane == 0) sred[threadIdx.x >> 5] = make_float2(nll, cnt);
    __syncthreads();
    if (threadIdx.x == 0) {
        float s = 0.f, c = 0.f;
#pragma unroll
        for (int i = 0; i < 8; i++) { s += sred[i].x; c += sred[i].y; }
        g_part[blockIdx.x] = make_float2(s, c);
        __threadfence();
        unsigned o = atomicAdd(&g_k3done, 1u);
        slast = (o == K1_BLOCKS - 1) ? 1u : 0u;
    }
    __syncthreads();
    if (slast) {
        __shared__ float ss[256], sc[256];
        __threadfence();
        float s = 0.f, c = 0.f;
        for (int i = threadIdx.x; i < K1_BLOCKS; i += 256) {
            float2 v = g_part[i];
            s += v.x; c += v.y;
        }
        ss[threadIdx.x] = s; sc[threadIdx.x] = c;
        __syncthreads();
        for (int st = 128; st; st >>= 1) {
            if (threadIdx.x < st) {
                ss[threadIdx.x] += ss[threadIdx.x + st];
                sc[threadIdx.x] += sc[threadIdx.x + st];
            }
            __syncthreads();
        }
        if (threadIdx.x == 0) out[0] = ss[0] / sc[0];
    }
}

// ============================================================================
extern "C" void kernel_launch(void* const* d_in, const int* in_sizes, int n_in,
                              void* d_out, int out_size) {
    const int*   items   = (const int*)d_in[0];
    const int*   actions = (const int*)d_in[1];
    const float* WihT    = (const float*)d_in[2];
    const float* Whh     = (const float*)d_in[3];
    const float* b_lstm  = (const float*)d_in[4];
    const float* temb    = (const float*)d_in[5];
    const float* Wq      = (const float*)d_in[6];
    const float* bq      = (const float*)d_in[7];
    (void)in_sizes; (void)n_in; (void)out_size;

    k1_prep<<<K1_BLOCKS, 256>>>(items, actions, WihT, b_lstm);
    knop<<<1, 1>>>();   // alignment: put k2_lstm at ncu's profiled slot (-s 5)
    knop<<<1, 1>>>();
    k2_lstm<<<NCL * CL, THR>>>(Whh);
    k3_loss<<<K1_BLOCKS, 256>>>(items, actions, temb, Wq, bq, (float*)d_out);
}